// round 2
// baseline (speedup 1.0000x reference)
#include <cuda_runtime.h>
#include <cuda_bf16.h>

// Repacked grid: [B=4][Hg=16][Wg=16][D=8][16ch(pad)] = 131072 floats
__device__ float g_repack[4 * 16 * 16 * 8 * 16];

__global__ void repack_kernel(const float* __restrict__ G) {
    int i = blockIdx.x * blockDim.x + threadIdx.x;  // 131072 threads
    int c = i & 15;
    int t = i >> 4;
    int z = t & 7;  t >>= 3;
    int x = t & 15; t >>= 4;
    int y = t & 15;
    int b = t >> 4;
    float v = 0.0f;
    if (c < 12) {
        // original layout: G[b][c][z][y][x], strides c:2048, z:256, y:16, x:1
        v = G[((b * 12 + c) * 8 + z) * 256 + y * 16 + x];
    }
    g_repack[i] = v;
}

// Shared layout: [sy(2)][sx(3)][z(8)] cells of 20 floats (12 used + 8 pad)
//   z-stride 20 floats (80B): z*20 mod 32 = {0,20,8,28,16,4,24,12} -> conflict-free
//   x-stride 164 floats, y-stride 492 floats. Total 984 floats = 3.9KB.
#define ZSTR 20
#define XSTR 164
#define YSTR 492

__global__ __launch_bounds__(256) void slice_apply_kernel(
    const float* __restrict__ guide,
    const float* __restrict__ fr,
    float* __restrict__ out)
{
    __shared__ float sh[2 * YSTR];  // 984 floats

    const int b  = blockIdx.z;
    const int tx = blockIdx.x;          // x grid-cell index (tile is 64 px wide)
    const int r0 = blockIdx.y << 4;     // tile start row (16 rows)

    // fy0 is uniform over the whole 16-row tile (boundaries at y = 32 + 64k,
    // which always coincide with a tile start).
    const float fy0f = floorf((float)(r0) * (1.0f / 64.0f) + (0.5f / 64.0f) - 0.5f);
    const int   fy0  = (int)fy0f;
    const int   iy0  = max(fy0, 0);
    const int   iy1  = min(fy0 + 1, 15);
    const int   ixs0 = max(tx - 1, 0);
    const int   ixs2 = min(tx + 1, 15);

    // ---- cooperative fill of shared grid footprint: 2y * 3x * 8z * 12c = 576 ----
    for (int i = threadIdx.x; i < 576; i += 256) {
        int c = i % 12;
        int t = i / 12;
        int z = t & 7; t >>= 3;
        int sx = t % 3;
        int sy = t / 3;
        int gy = sy ? iy1 : iy0;
        int gx = (sx == 0) ? ixs0 : ((sx == 1) ? tx : ixs2);
        sh[sy * YSTR + sx * XSTR + z * ZSTR + c] =
            g_repack[(((b * 16 + gy) * 16 + gx) * 8 + z) * 16 + c];
    }
    __syncthreads();

    // ---- per-thread: 4 consecutive x pixels ----
    const int row = threadIdx.x >> 4;           // 0..15
    const int xq  = (threadIdx.x & 15) << 2;    // 0..60
    const int y   = r0 + row;
    const int x   = (tx << 6) + xq;

    const float gyv = ((float)y + 0.5f) * (1.0f / 64.0f) - 0.5f;
    const float wy  = gyv - fy0f;

    // fx0 uniform per quad: floor((x-31.5)/64) = tx-1 if xq<32 else tx
    const int   sx0  = (xq >= 32) ? 1 : 0;
    const float fx0f = (float)(tx - 1 + sx0);

    const size_t pixBase = ((size_t)b * 1048576u) + ((size_t)y << 10) + (size_t)x;
    const float4 g4 = *(const float4*)&guide[pixBase];
    const size_t frBase = ((size_t)b * 3u) * 1048576u + ((size_t)y << 10) + (size_t)x;
    const float4 fc0 = *(const float4*)&fr[frBase];
    const float4 fc1 = *(const float4*)&fr[frBase + 1048576u];
    const float4 fc2 = *(const float4*)&fr[frBase + 2097152u];

    const float gArr[4]  = {g4.x, g4.y, g4.z, g4.w};
    const float f0a[4]   = {fc0.x, fc0.y, fc0.z, fc0.w};
    const float f1a[4]   = {fc1.x, fc1.y, fc1.z, fc1.w};
    const float f2a[4]   = {fc2.x, fc2.y, fc2.z, fc2.w};

    float o0[4], o1[4], o2[4];

    #pragma unroll
    for (int p = 0; p < 4; p++) {
        const float gxv = ((float)(x + p) + 0.5f) * (1.0f / 64.0f) - 0.5f;
        const float wx  = gxv - fx0f;

        const float g    = gArr[p];
        const float gz   = g * 8.0f - 0.5f;
        const float fz0f = floorf(gz);
        const float wz   = gz - fz0f;
        const int   fz0  = (int)fz0f;
        const int   z0   = max(fz0, 0);
        const int   z1   = min(fz0 + 1, 7);

        const float f0p = f0a[p], f1p = f1a[p], f2p = f2a[p];

        float a0 = 0.0f, a1 = 0.0f, a2 = 0.0f;

        #pragma unroll
        for (int zi = 0; zi < 2; zi++) {
            const int   zb  = (zi ? z1 : z0) * ZSTR;
            const float wzc = zi ? wz : (1.0f - wz);
            #pragma unroll
            for (int syi = 0; syi < 2; syi++) {
                const float wzy = wzc * (syi ? wy : (1.0f - wy));
                const int   yb  = syi * YSTR + zb;
                #pragma unroll
                for (int sxi = 0; sxi < 2; sxi++) {
                    const float w = wzy * (sxi ? wx : (1.0f - wx));
                    const int base = yb + (sx0 + sxi) * XSTR;
                    const float4 A  = *(const float4*)&sh[base];
                    const float4 Bv = *(const float4*)&sh[base + 4];
                    const float4 Cv = *(const float4*)&sh[base + 8];
                    a0 += w * (A.x  * f0p + A.y  * f1p + A.z  * f2p + A.w);
                    a1 += w * (Bv.x * f0p + Bv.y * f1p + Bv.z * f2p + Bv.w);
                    a2 += w * (Cv.x * f0p + Cv.y * f1p + Cv.z * f2p + Cv.w);
                }
            }
        }
        o0[p] = a0; o1[p] = a1; o2[p] = a2;
    }

    float4* outp = (float4*)&out[frBase];
    *outp = make_float4(o0[0], o0[1], o0[2], o0[3]);
    outp = (float4*)&out[frBase + 1048576u];
    *outp = make_float4(o1[0], o1[1], o1[2], o1[3]);
    outp = (float4*)&out[frBase + 2097152u];
    *outp = make_float4(o2[0], o2[1], o2[2], o2[3]);
}

extern "C" void kernel_launch(void* const* d_in, const int* in_sizes, int n_in,
                              void* d_out, int out_size) {
    // Identify inputs by element count (metadata order: grid, guide, fr)
    const float* G     = nullptr;
    const float* guide = nullptr;
    const float* fr    = nullptr;
    for (int i = 0; i < n_in; i++) {
        if (in_sizes[i] == 98304)          G     = (const float*)d_in[i];
        else if (in_sizes[i] == 4194304)   guide = (const float*)d_in[i];
        else if (in_sizes[i] == 12582912)  fr    = (const float*)d_in[i];
    }
    if (!G)     G     = (const float*)d_in[0];
    if (!guide) guide = (const float*)d_in[1];
    if (!fr)    fr    = (const float*)d_in[2];

    float* out = (float*)d_out;

    repack_kernel<<<512, 256>>>(G);

    dim3 grid(16, 64, 4);   // x-tiles(64px), y-tiles(16rows), batch
    slice_apply_kernel<<<grid, 256>>>(guide, fr, out);
}